// round 7
// baseline (speedup 1.0000x reference)
#include <cuda_runtime.h>
#include <cstdint>

#define NN 256      // batch
#define PP 128      // points per polygon (= segments)
#define TPB 512
#define NB  NN
#define SCH (PP / 4)      // 32 segments per h-chunk
#define PCH (PP / 4)      // 32 preds per h-chunk

__device__ float4 g_part[NN];
__device__ unsigned int g_cnt = 0;

__device__ __forceinline__ float smooth_l1(float p, float t) {
    float d = fabsf(p - t);
    return d < 0.25f ? 2.0f * d * d : d - 0.125f;   // BETA = 0.25
}

__device__ __forceinline__ unsigned long long pack2(float lo, float hi) {
    unsigned long long r;
    asm("mov.b64 %0, {%1, %2};" : "=l"(r)
        : "r"(__float_as_uint(lo)), "r"(__float_as_uint(hi)));
    return r;
}
__device__ __forceinline__ unsigned long long fma2(unsigned long long a,
                                                   unsigned long long b,
                                                   unsigned long long c) {
    unsigned long long r;
    asm("fma.rn.f32x2 %0, %1, %2, %3;" : "=l"(r) : "l"(a), "l"(b), "l"(c));
    return r;
}
__device__ __forceinline__ void unpack2(unsigned long long v, float& lo, float& hi) {
    unsigned int a, b;
    asm("mov.b64 {%0, %1}, %2;" : "=r"(a), "=r"(b) : "l"(v));
    lo = __uint_as_float(a); hi = __uint_as_float(b);
}

__global__ void __launch_bounds__(TPB, 2) dm_fused(
    const float* __restrict__ pred_c,
    const float* __restrict__ pred_o,
    const float* __restrict__ gt_c,
    const float* __restrict__ gt_k,
    const int*   __restrict__ gt_m,
    float*       __restrict__ out)
{
    // packed segment tables:
    //   T1 = (-2bx, -2dx, -2by, -2dy)   T2 = (|b|^2, 2 b·d, gamma, -0.5/gamma)
    // score(pred,k) = alpha + beta*k + gamma*k^2,  (alpha,beta) via 2x fma.f32x2
    __shared__ float4 s_T1[PP], s_T2[PP];
    __shared__ float4 s_pt[PP];                 // pred score table (-2px,-2py,|p|^2,0)
    __shared__ float2 s_pred[PP], s_po[PP], s_gk[PP];
    __shared__ int    s_mk[PP];
    __shared__ float  s_bs[4 * PP];
    __shared__ float  s_bi[4 * PP];             // packed float index 16*sg + k
    __shared__ float  s_b2[4 * PP];
    __shared__ int    s_j2[4 * PP];
    __shared__ float  s_red[4][16];
    __shared__ int    s_last;

    const int n = blockIdx.x;
    const int t = threadIdx.x;
    const int p = t & (PP - 1);
    const int h = t >> 7;           // chunk 0..3 (uniform per warp -> broadcast LDS)

    // ---- fused prologue: one 128-thread phase, one barrier ----
    if (t < PP) {
        const float2* pc2 = reinterpret_cast<const float2*>(pred_c) + (size_t)n * PP;
        const float2* po2 = reinterpret_cast<const float2*>(pred_o) + (size_t)n * PP;
        const float2* gc2 = reinterpret_cast<const float2*>(gt_c)   + (size_t)n * PP;
        const float2* gk2 = reinterpret_cast<const float2*>(gt_k)   + (size_t)n * PP;
        float2 pr = pc2[t];
        s_pred[t] = pr;
        s_pt[t]   = make_float4(-2.0f * pr.x, -2.0f * pr.y,
                                pr.x * pr.x + pr.y * pr.y, 0.0f);
        s_po[t]   = po2[t];
        s_gk[t]   = gk2[t];
        s_mk[t]   = gt_m[(size_t)n * PP + t];
        float2 a  = gc2[t];
        float2 b  = gc2[(t + PP - 1) & (PP - 1)];   // neighbor from L2, no smem hop
        float dx = (a.x - b.x) * 0.1f;
        float dy = (a.y - b.y) * 0.1f;
        float g2 = dx * dx + dy * dy;
        float inv = (g2 > 0.0f) ? (-0.5f / g2) : 0.0f;
        s_T1[t] = make_float4(-2.0f * b.x, -2.0f * dx, -2.0f * b.y, -2.0f * dy);
        s_T2[t] = make_float4(b.x * b.x + b.y * b.y,
                              2.0f * (b.x * dx + b.y * dy), g2, inv);
    }
    __syncthreads();

    // ---- item 1: chunk h of segments, closed-form best k per segment ----
    const float px = s_pred[p].x, py = s_pred[p].y;
    {
        const unsigned long long pxx = pack2(px, px);
        const unsigned long long pyy = pack2(py, py);
        const int base = h * SCH;
        float val[4]; float bif[4];
        #pragma unroll
        for (int u = 0; u < 4; ++u) { val[u] = 3.4e38f; bif[u] = 0.0f; }
        #pragma unroll
        for (int j = 0; j < SCH; j += 4) {
            #pragma unroll
            for (int u = 0; u < 4; ++u) {
                const int sg = base + j + u;
                const ulonglong2 q1 = *reinterpret_cast<const ulonglong2*>(&s_T1[sg]);
                const ulonglong2 q2 = *reinterpret_cast<const ulonglong2*>(&s_T2[sg]);
                unsigned long long ab = fma2(pyy, q1.y, q2.x);
                ab = fma2(pxx, q1.x, ab);
                float alpha, beta;  unpack2(ab, alpha, beta);
                float gam, inv;     unpack2(q2.y, gam, inv);
                float kf = beta * inv;                      // vertex
                kf = fminf(fmaxf(kf, 0.0f), 9.0f);
                kf = rintf(kf);
                float v = fmaf(kf, fmaf(kf, gam, beta), alpha);
                float bi = kf + (float)(16 * (j + u));      // chunk-local, imm FADD
                if (v < val[u]) { val[u] = v; bif[u] = bi; }
            }
        }
        float bs = val[0]; float bi = bif[0];
        #pragma unroll
        for (int u = 1; u < 4; ++u)
            if (val[u] < bs || (val[u] == bs && bif[u] < bi)) { bs = val[u]; bi = bif[u]; }
        s_bs[t] = bs;
        s_bi[t] = bi + (float)(h * 512);    // add chunk base once (exact ints)
    }

    // ---- item 2: chunk h of preds for key point p (score form) ----
    {
        const float kx = s_gk[p].x, ky = s_gk[p].y;
        const int pb = h * PCH;
        float b2[4]; int j2[4];
        #pragma unroll
        for (int u = 0; u < 4; ++u) { b2[u] = 3.4e38f; j2[u] = 0; }
        #pragma unroll
        for (int j = 0; j < PCH; j += 4) {
            #pragma unroll
            for (int u = 0; u < 4; ++u) {
                float4 E = s_pt[pb + j + u];
                float d = fmaf(kx, E.x, fmaf(ky, E.y, E.z));
                if (d < b2[u]) { b2[u] = d; j2[u] = pb + j + u; }
            }
        }
        float bs = b2[0]; int bi = j2[0];
        #pragma unroll
        for (int u = 1; u < 4; ++u)
            if (b2[u] < bs || (b2[u] == bs && j2[u] < bi)) { bs = b2[u]; bi = j2[u]; }
        s_b2[t] = bs; s_j2[t] = bi;
    }
    __syncthreads();

    // ---- split tail: h==0 threads do item1 loss, h==1 threads do item2 loss ----
    float s1 = 0.0f, c1 = 0.0f, s2 = 0.0f, c2 = 0.0f;
    if (h == 0) {
        float bs = s_bs[p]; float bif = s_bi[p];
        #pragma unroll
        for (int hh = 1; hh < 4; ++hh) {
            float s = s_bs[hh * PP + p]; float b = s_bi[hh * PP + p];
            if (s < bs || (s == bs && b < bif)) { bs = s; bif = b; }
        }
        int bi = (int)bif;
        int sg = bi >> 4;
        float kf = (float)(bi & 15);
        float4 T1 = s_T1[sg];                   // (-2bx,-2dx,-2by,-2dy)
        float tx = -0.5f * fmaf(kf, T1.y, T1.x);
        float ty = -0.5f * fmaf(kf, T1.w, T1.z);
        float mpx = s_pred[p].x, mpy = s_pred[p].y;
        float dxx = mpx - tx, dyy = mpy - ty;
        float d2 = dxx * dxx + dyy * dyy;
        if (d2 <= 1.0e6f) {
            float2 mo = s_po[p];
            float ox = (tx - mpx) * 0.25f;
            float oy = (ty - mpy) * 0.25f;
            s1 = smooth_l1(mo.x, ox) + smooth_l1(mo.y, oy);
            c1 = 1.0f;
        }
    } else if (h == 1) {
        float b2m = s_b2[p]; int j2m = s_j2[p];
        #pragma unroll
        for (int hh = 1; hh < 4; ++hh) {
            float s = s_b2[hh * PP + p]; int j = s_j2[hh * PP + p];
            if (s < b2m || (s == b2m && j < j2m)) { b2m = s; j2m = j; }
        }
        float2 kk = s_gk[p];
        float kk2 = kk.x * kk.x + kk.y * kk.y;  // restore true dist^2
        if (s_mk[p] && (b2m + kk2) <= 1.0e6f) {
            float2 pg = s_pred[j2m];
            float2 og = s_po[j2m];
            float ox = (kk.x - pg.x) * 0.25f;
            float oy = (kk.y - pg.y) * 0.25f;
            s2 = smooth_l1(og.x, ox) + smooth_l1(og.y, oy);
            c2 = 1.0f;
        }
    }

    // ---- deterministic block reduction over all 16 warps ----
    #pragma unroll
    for (int o = 16; o > 0; o >>= 1) {
        s1 += __shfl_down_sync(0xffffffffu, s1, o);
        c1 += __shfl_down_sync(0xffffffffu, c1, o);
        s2 += __shfl_down_sync(0xffffffffu, s2, o);
        c2 += __shfl_down_sync(0xffffffffu, c2, o);
    }
    const int w = t >> 5, l = t & 31;
    if (l == 0) {
        s_red[0][w] = s1; s_red[1][w] = c1;
        s_red[2][w] = s2; s_red[3][w] = c2;
    }
    __syncthreads();
    if (t == 0) {
        float a0 = 0.f, a1 = 0.f, a2 = 0.f, a3 = 0.f;
        #pragma unroll
        for (int i = 0; i < 16; ++i) {
            a0 += s_red[0][i]; a1 += s_red[1][i];
            a2 += s_red[2][i]; a3 += s_red[3][i];
        }
        g_part[n] = make_float4(a0, a1, a2, a3);
        __threadfence();
        unsigned int v = atomicAdd(&g_cnt, 1u);
        s_last = (v == (unsigned)(NB - 1));
    }
    __syncthreads();

    // ---- last block: fixed-order final reduction (bitwise deterministic) ----
    if (s_last) {
        float f1 = 0.f, f2 = 0.f, f3 = 0.f, f4 = 0.f;
        if (t < NN) {
            float4 v = g_part[t];
            f1 = v.x; f2 = v.y; f3 = v.z; f4 = v.w;
        }
        #pragma unroll
        for (int o = 16; o > 0; o >>= 1) {
            f1 += __shfl_down_sync(0xffffffffu, f1, o);
            f2 += __shfl_down_sync(0xffffffffu, f2, o);
            f3 += __shfl_down_sync(0xffffffffu, f3, o);
            f4 += __shfl_down_sync(0xffffffffu, f4, o);
        }
        __syncthreads();
        if (l == 0) {
            s_red[0][w] = f1; s_red[1][w] = f2;
            s_red[2][w] = f3; s_red[3][w] = f4;
        }
        __syncthreads();
        if (t == 0) {
            float t1 = 0.f, t2 = 0.f, t3 = 0.f, t4 = 0.f;
            #pragma unroll
            for (int i = 0; i < 16; ++i) {
                t1 += s_red[0][i]; t2 += s_red[1][i];
                t3 += s_red[2][i]; t4 += s_red[3][i];
            }
            float loss1 = (t1 / fmaxf(t2 * 2.0f, 1.0f)) * 0.5f;  // * (1 - KEY_W)
            float loss2 = (t3 / fmaxf(t4 * 2.0f, 1.0f)) * 0.5f;  // * KEY_W
            out[0] = loss1 + loss2;
            g_cnt = 0;   // reset for next graph replay
        }
    }
}

extern "C" void kernel_launch(void* const* d_in, const int* in_sizes, int n_in,
                              void* d_out, int out_size)
{
    const float* pred_c = (const float*)d_in[0];
    const float* pred_o = (const float*)d_in[1];
    const float* gt_c   = (const float*)d_in[2];
    const float* gt_k   = (const float*)d_in[3];
    const int*   gt_m   = (const int*)d_in[4];

    dm_fused<<<NB, TPB>>>(pred_c, pred_o, gt_c, gt_k, gt_m, (float*)d_out);
}

// round 8
// speedup vs baseline: 1.1274x; 1.1274x over previous
#include <cuda_runtime.h>
#include <cstdint>

#define NN 256      // batch
#define PP 128      // points per polygon (= segments)
#define TPB 512
#define NB  NN
#define SCH (PP / 4)      // 32 segments per h-chunk
#define PCH (PP / 4)      // 32 preds per h-chunk
#define MAGIC 12582912.0f // 2^23 + 2^22, bits 0x4B400000

__device__ float4 g_part[NN];
__device__ unsigned int g_cnt = 0;

__device__ __forceinline__ float smooth_l1(float p, float t) {
    float d = fabsf(p - t);
    return d < 0.25f ? 2.0f * d * d : d - 0.125f;   // BETA = 0.25
}

__device__ __forceinline__ unsigned long long pack2(float lo, float hi) {
    unsigned long long r;
    asm("mov.b64 %0, {%1, %2};" : "=l"(r)
        : "r"(__float_as_uint(lo)), "r"(__float_as_uint(hi)));
    return r;
}
__device__ __forceinline__ unsigned long long fma2(unsigned long long a,
                                                   unsigned long long b,
                                                   unsigned long long c) {
    unsigned long long r;
    asm("fma.rn.f32x2 %0, %1, %2, %3;" : "=l"(r) : "l"(a), "l"(b), "l"(c));
    return r;
}
__device__ __forceinline__ void unpack2(unsigned long long v, float& lo, float& hi) {
    unsigned int a, b;
    asm("mov.b64 {%0, %1}, %2;" : "=r"(a), "=r"(b) : "l"(v));   // reg-pair alias, free
    lo = __uint_as_float(a); hi = __uint_as_float(b);
}

__global__ void __launch_bounds__(TPB, 2) dm_fused(
    const float* __restrict__ pred_c,
    const float* __restrict__ pred_o,
    const float* __restrict__ gt_c,
    const float* __restrict__ gt_k,
    const int*   __restrict__ gt_m,
    float*       __restrict__ out)
{
    // packed segment tables:
    //   T1 = (-2bx, -2dx, -2by, -2dy)   T2 = (|b|^2, 2 b·d, gamma, -0.5/gamma)
    // score(pred,k) = alpha + beta*k + gamma*k^2 -> closed-form k*
    __shared__ float4 s_T1[PP], s_T2[PP];
    __shared__ float4 s_pt[PP];                 // pred score table (-2px,-2py,|p|^2,0)
    __shared__ float2 s_pred[PP], s_po[PP], s_gk[PP];
    __shared__ int    s_mk[PP];
    __shared__ float  s_bs[4 * PP];             // item1 keys (score | local idx)
    __shared__ float  s_b2[4 * PP];             // item2 keys (score | pred idx)
    __shared__ float  s_red[4][16];
    __shared__ int    s_last;

    const int n = blockIdx.x;
    const int t = threadIdx.x;
    const int p = t & (PP - 1);
    const int h = t >> 7;           // chunk 0..3 (uniform per warp -> broadcast LDS)

    // ---- fused prologue: one 128-thread phase, one barrier ----
    if (t < PP) {
        const float2* pc2 = reinterpret_cast<const float2*>(pred_c) + (size_t)n * PP;
        const float2* po2 = reinterpret_cast<const float2*>(pred_o) + (size_t)n * PP;
        const float2* gc2 = reinterpret_cast<const float2*>(gt_c)   + (size_t)n * PP;
        const float2* gk2 = reinterpret_cast<const float2*>(gt_k)   + (size_t)n * PP;
        float2 pr = pc2[t];
        s_pred[t] = pr;
        s_pt[t]   = make_float4(-2.0f * pr.x, -2.0f * pr.y,
                                pr.x * pr.x + pr.y * pr.y, 0.0f);
        s_po[t]   = po2[t];
        s_gk[t]   = gk2[t];
        s_mk[t]   = gt_m[(size_t)n * PP + t];
        float2 a  = gc2[t];
        float2 b  = gc2[(t + PP - 1) & (PP - 1)];   // neighbor from L2
        float dx = (a.x - b.x) * 0.1f;
        float dy = (a.y - b.y) * 0.1f;
        float g2 = dx * dx + dy * dy;
        float inv = (g2 > 0.0f) ? (-0.5f / g2) : 0.0f;
        s_T1[t] = make_float4(-2.0f * b.x, -2.0f * dx, -2.0f * b.y, -2.0f * dy);
        s_T2[t] = make_float4(b.x * b.x + b.y * b.y,
                              2.0f * (b.x * dx + b.y * dy), g2, inv);
    }
    __syncthreads();

    // ---- item 1: chunk h of segments; key = quantized score | (local_sg<<4 | k) ----
    const float px = s_pred[p].x, py = s_pred[p].y;
    {
        const unsigned long long pxx = pack2(px, px);
        const unsigned long long pyy = pack2(py, py);
        const int base = h * SCH;
        float bk[4];
        #pragma unroll
        for (int u = 0; u < 4; ++u) bk[u] = 3.4e38f;
        #pragma unroll
        for (int j = 0; j < SCH; j += 4) {
            #pragma unroll
            for (int u = 0; u < 4; ++u) {
                const int sg = base + j + u;
                const ulonglong2 q1 = *reinterpret_cast<const ulonglong2*>(&s_T1[sg]);
                const ulonglong2 q2 = *reinterpret_cast<const ulonglong2*>(&s_T2[sg]);
                unsigned long long ab = fma2(pyy, q1.y, q2.x);
                ab = fma2(pxx, q1.x, ab);
                float alpha, beta;  unpack2(ab, alpha, beta);
                float gam, inv;     unpack2(q2.y, gam, inv);
                float kf = beta * inv;                      // vertex
                kf = fminf(fmaxf(kf, 0.0f), 9.0f);
                float mrd = kf + MAGIC;                     // magic round (RNE)
                float kr  = mrd - MAGIC;
                float v = fmaf(kr, fmaf(kr, gam, beta), alpha);
                // k = mantissa bits of mrd; local idx = 16*(j+u) + k  (IADD, imm folded)
                int kp = __float_as_int(mrd) + (16 * (j + u) - 0x4B400000);
                float key = __uint_as_float(
                    (__float_as_uint(v) & 0xFFFFFE00u) | (unsigned)kp);
                bk[u] = fminf(bk[u], key);                  // FMNMX: 1-op track
            }
        }
        s_bs[t] = fminf(fminf(bk[0], bk[1]), fminf(bk[2], bk[3]));
    }

    // ---- item 2: chunk h of preds; key = quantized score | pred idx ----
    {
        const float kx = s_gk[p].x, ky = s_gk[p].y;
        const int pb = h * PCH;
        float bk[4];
        #pragma unroll
        for (int u = 0; u < 4; ++u) bk[u] = 3.4e38f;
        #pragma unroll
        for (int j = 0; j < PCH; j += 4) {
            #pragma unroll
            for (int u = 0; u < 4; ++u) {
                const int pj = pb + j + u;                  // IADD, imm folded
                float4 E = s_pt[pj];
                float d = fmaf(kx, E.x, fmaf(ky, E.y, E.z));
                float key = __uint_as_float(
                    (__float_as_uint(d) & 0xFFFFFF80u) | (unsigned)pj);
                bk[u] = fminf(bk[u], key);
            }
        }
        s_b2[t] = fminf(fminf(bk[0], bk[1]), fminf(bk[2], bk[3]));
    }
    __syncthreads();

    // ---- split tail: h==0 -> item1 loss, h==1 -> item2 loss ----
    float s1 = 0.0f, c1 = 0.0f, s2 = 0.0f, c2 = 0.0f;
    if (h == 0) {
        float bk = s_bs[p]; int bh = 0;
        #pragma unroll
        for (int hh = 1; hh < 4; ++hh) {
            float o = s_bs[hh * PP + p];
            if (o < bk) { bk = o; bh = hh; }                // keys unique per chunk
        }
        int loc = __float_as_int(bk) & 0x1FF;               // local_sg<<4 | k
        int sg  = (loc >> 4) + bh * SCH;
        float kf = (float)(loc & 15);
        float4 T1 = s_T1[sg];                               // (-2bx,-2dx,-2by,-2dy)
        float tx = -0.5f * fmaf(kf, T1.y, T1.x);
        float ty = -0.5f * fmaf(kf, T1.w, T1.z);
        float mpx = s_pred[p].x, mpy = s_pred[p].y;
        float dxx = mpx - tx, dyy = mpy - ty;
        float d2 = dxx * dxx + dyy * dyy;                   // exact matched dist^2
        if (d2 <= 1.0e6f) {
            float2 mo = s_po[p];
            float ox = (tx - mpx) * 0.25f;
            float oy = (ty - mpy) * 0.25f;
            s1 = smooth_l1(mo.x, ox) + smooth_l1(mo.y, oy);
            c1 = 1.0f;
        }
    } else if (h == 1) {
        float bk = s_b2[p];
        #pragma unroll
        for (int hh = 1; hh < 4; ++hh) bk = fminf(bk, s_b2[hh * PP + p]);
        int j2m = __float_as_int(bk) & 0x7F;                // global pred idx
        float2 kk = s_gk[p];
        float2 pg = s_pred[j2m];
        float dxx = kk.x - pg.x, dyy = kk.y - pg.y;
        float d2 = dxx * dxx + dyy * dyy;                   // exact matched dist^2
        if (s_mk[p] && d2 <= 1.0e6f) {
            float2 og = s_po[j2m];
            float ox = dxx * 0.25f;
            float oy = dyy * 0.25f;
            s2 = smooth_l1(og.x, ox) + smooth_l1(og.y, oy);
            c2 = 1.0f;
        }
    }

    // ---- deterministic block reduction over all 16 warps ----
    #pragma unroll
    for (int o = 16; o > 0; o >>= 1) {
        s1 += __shfl_down_sync(0xffffffffu, s1, o);
        c1 += __shfl_down_sync(0xffffffffu, c1, o);
        s2 += __shfl_down_sync(0xffffffffu, s2, o);
        c2 += __shfl_down_sync(0xffffffffu, c2, o);
    }
    const int w = t >> 5, l = t & 31;
    if (l == 0) {
        s_red[0][w] = s1; s_red[1][w] = c1;
        s_red[2][w] = s2; s_red[3][w] = c2;
    }
    __syncthreads();
    if (t == 0) {
        float a0 = 0.f, a1 = 0.f, a2 = 0.f, a3 = 0.f;
        #pragma unroll
        for (int i = 0; i < 16; ++i) {
            a0 += s_red[0][i]; a1 += s_red[1][i];
            a2 += s_red[2][i]; a3 += s_red[3][i];
        }
        g_part[n] = make_float4(a0, a1, a2, a3);
        __threadfence();
        unsigned int v = atomicAdd(&g_cnt, 1u);
        s_last = (v == (unsigned)(NB - 1));
    }
    __syncthreads();

    // ---- last block: fixed-order final reduction (bitwise deterministic) ----
    if (s_last) {
        float f1 = 0.f, f2 = 0.f, f3 = 0.f, f4 = 0.f;
        if (t < NN) {
            float4 v = g_part[t];
            f1 = v.x; f2 = v.y; f3 = v.z; f4 = v.w;
        }
        #pragma unroll
        for (int o = 16; o > 0; o >>= 1) {
            f1 += __shfl_down_sync(0xffffffffu, f1, o);
            f2 += __shfl_down_sync(0xffffffffu, f2, o);
            f3 += __shfl_down_sync(0xffffffffu, f3, o);
            f4 += __shfl_down_sync(0xffffffffu, f4, o);
        }
        __syncthreads();
        if (l == 0) {
            s_red[0][w] = f1; s_red[1][w] = f2;
            s_red[2][w] = f3; s_red[3][w] = f4;
        }
        __syncthreads();
        if (t == 0) {
            float t1 = 0.f, t2 = 0.f, t3 = 0.f, t4 = 0.f;
            #pragma unroll
            for (int i = 0; i < 16; ++i) {
                t1 += s_red[0][i]; t2 += s_red[1][i];
                t3 += s_red[2][i]; t4 += s_red[3][i];
            }
            float loss1 = (t1 / fmaxf(t2 * 2.0f, 1.0f)) * 0.5f;  // * (1 - KEY_W)
            float loss2 = (t3 / fmaxf(t4 * 2.0f, 1.0f)) * 0.5f;  // * KEY_W
            out[0] = loss1 + loss2;
            g_cnt = 0;   // reset for next graph replay
        }
    }
}

extern "C" void kernel_launch(void* const* d_in, const int* in_sizes, int n_in,
                              void* d_out, int out_size)
{
    const float* pred_c = (const float*)d_in[0];
    const float* pred_o = (const float*)d_in[1];
    const float* gt_c   = (const float*)d_in[2];
    const float* gt_k   = (const float*)d_in[3];
    const int*   gt_m   = (const int*)d_in[4];

    dm_fused<<<NB, TPB>>>(pred_c, pred_o, gt_c, gt_k, gt_m, (float*)d_out);
}